// round 1
// baseline (speedup 1.0000x reference)
#include <cuda_runtime.h>

// x:   [B, N, 128] f32  -> viewed as [B*N, 32] float4
// R:   [B, N, 2, 2] f32 -> viewed as [B*N] float4 (r00, r01, r10, r11)
// out: same shape as x.
// y0 = r00*x0 + r01*x1 ; y1 = r10*x0 + r11*x1 for each consecutive pair.

__global__ __launch_bounds__(256) void rot2_kernel(
    const float4* __restrict__ x,
    const float4* __restrict__ R,
    float4* __restrict__ out,
    int n4)
{
    int i = blockIdx.x * blockDim.x + threadIdx.x;
    if (i >= n4) return;

    int point = i >> 5;                 // 32 float4 per point (128 floats)
    float4 r = __ldg(&R[point]);        // broadcast within the warp-group
    float4 v = __ldg(&x[i]);

    float4 o;
    o.x = fmaf(r.x, v.x, r.y * v.y);    // pair 0: y0
    o.y = fmaf(r.z, v.x, r.w * v.y);    // pair 0: y1
    o.z = fmaf(r.x, v.z, r.y * v.w);    // pair 1: y0
    o.w = fmaf(r.z, v.z, r.w * v.w);    // pair 1: y1
    out[i] = o;
}

extern "C" void kernel_launch(void* const* d_in, const int* in_sizes, int n_in,
                              void* d_out, int out_size)
{
    const float4* x = (const float4*)d_in[0];
    const float4* R = (const float4*)d_in[1];
    float4* out = (float4*)d_out;

    int n4 = out_size / 4;              // number of float4 elements
    int threads = 256;
    int blocks = (n4 + threads - 1) / threads;
    rot2_kernel<<<blocks, threads>>>(x, R, out, n4);
}